// round 3
// baseline (speedup 1.0000x reference)
#include <cuda_runtime.h>
#include <math.h>
#include <stdint.h>

// ---------------- problem constants ----------------
#define BSZ   64
#define HD    1024
#define ED    512
#define SRCL  128
#define TGTL  128
#define NJ4   4096              // 4*HD
#define NBLK  128               // persistent blocks (<= 148 SMs -> co-resident)
#define OUT_MAIN (TGTL*BSZ*HD)  // 8388608

// ---------------- device scratch (static, no allocs) ----------------
__device__ float g_Wenc0[1536*4096];   // k-major concat(Wih0, Whh0)
__device__ float g_Wenc1[2048*4096];
__device__ float g_Wdec0[1536*4096];
__device__ float g_Wdec1[2048*4096];
__device__ float g_linWT[1024*1024];   // [k][j] = dec_linW[j][k]
__device__ float g_zpart[2097152];     // K-split partials
__device__ float g_h0[BSZ*HD], g_c0[BSZ*HD], g_h1[BSZ*HD], g_c1[BSZ*HD];
__device__ int   g_deint[BSZ];
__device__ float g_nll[TGTL*BSZ];
__device__ unsigned g_cnt;             // barrier arrive count (returns to 0)
__device__ volatile unsigned g_gen;    // barrier generation (monotonic)

// ---------------- helpers ----------------
__device__ __forceinline__ float sigm(float x) { return 1.0f / (1.0f + expf(-x)); }

__device__ __forceinline__ unsigned long long fma2(unsigned long long a,
                                                   unsigned long long b,
                                                   unsigned long long c) {
    unsigned long long d;
    asm("fma.rn.f32x2 %0, %1, %2, %3;" : "=l"(d) : "l"(a), "l"(b), "l"(c));
    return d;
}
__device__ __forceinline__ unsigned long long bcast2(float x) {
    unsigned long long r;
    asm("mov.b64 %0, {%1, %1};" : "=l"(r) : "r"(__float_as_uint(x)));
    return r;
}

union F4U { float4 f; unsigned long long u[2]; };

// ---------------- software grid barrier (all NBLK blocks co-resident) ----------------
__device__ __forceinline__ void gsync() {
    __syncthreads();
    if (threadIdx.x == 0) {
        __threadfence();
        unsigned gen = g_gen;
        if (atomicAdd(&g_cnt, 1u) == NBLK - 1u) {
            g_cnt = 0u;
            __threadfence();
            g_gen = gen + 1u;
        } else {
            while (g_gen == gen) { __nanosleep(64); }
        }
        __threadfence();
    }
    __syncthreads();
}

// ---------------- in-kernel tiled transpose: dst[k*S + j] = src[j*C + k] ----------------
__device__ void transp(float* __restrict__ dst, int dstStride,
                       const float* __restrict__ src, int R, int C,
                       float* tile, int bid) {
    int tx = threadIdx.x & 31, ty = threadIdx.x >> 5;   // 32 x 8
    int tilesK = C >> 5, tilesJ = R >> 5;
    int ntiles = tilesK * tilesJ;
    for (int tt = bid; tt < ntiles; tt += NBLK) {
        int k0 = (tt % tilesK) << 5;
        int j0 = (tt / tilesK) << 5;
        __syncthreads();
#pragma unroll
        for (int i = 0; i < 4; i++) {
            int j = j0 + ty + i * 8;
            tile[(ty + i * 8) * 33 + tx] = src[(size_t)j * C + k0 + tx];
        }
        __syncthreads();
#pragma unroll
        for (int i = 0; i < 4; i++) {
            int k = k0 + ty + i * 8;
            dst[(size_t)k * dstStride + j0 + tx] = tile[tx * 33 + ty + i * 8];
        }
    }
}

// ---------------- fused-K GEMM tile (one block = 64b x 256j, one K chunk) ----------------
// z[b][j] += sum_{k in chunk} xcat[b][k] * W[k][j]
// xcat[b][k] = (k < K1) ? xbase[row(b)*K1 + k] : hsrc[b*HD + (k-K1)]
__device__ __forceinline__ void gemm_phase(
    const float* __restrict__ W,
    const float* __restrict__ xbase,
    const int* __restrict__ ids, int id_stride, int id_off,
    int K1, const float* __restrict__ hsrc,
    int kchunk, int NJ,
    float* __restrict__ zpart, int jtile, int ksplit,
    float* Xs, float* Ws) {

    int t = threadIdx.x;
    int jbase = jtile * 256;
    int kbase = ksplit * kchunk;

    int jg = t & 31;
    int bg = t >> 5;
    int b0 = bg * 8;
    int j0a = jg * 4;
    int j0b = j0a + 128;

    int lb = t >> 2;
    int lq = t & 3;
    const float* xrow;
    {
        int row = ids ? ids[lb * id_stride + id_off] : lb;
        xrow = xbase + (size_t)row * K1;
    }

    unsigned long long acc[8][4];
#pragma unroll
    for (int i = 0; i < 8; i++)
#pragma unroll
        for (int j = 0; j < 4; j++) acc[i][j] = 0ull;

    for (int kt = 0; kt < kchunk; kt += 16) {
        int kg = kbase + kt;
        // W tile: 16 x 256 (k-major, coalesced)
#pragma unroll
        for (int i = 0; i < 4; i++) {
            int idx = t + i * 256;
            int r = idx >> 6;
            int c = (idx & 63) << 2;
            *(float4*)&Ws[r * 256 + c] = *(const float4*)&W[(size_t)(kg + r) * NJ + jbase + c];
        }
        // X tile: 16k x 64b (chunks 16-aligned, never straddle K1)
        {
            int k0 = kg + lq * 4;
            float4 v;
            if (k0 < K1) v = *(const float4*)&xrow[k0];
            else         v = *(const float4*)&hsrc[lb * HD + (k0 - K1)];
            Xs[(lq * 4 + 0) * 64 + lb] = v.x;
            Xs[(lq * 4 + 1) * 64 + lb] = v.y;
            Xs[(lq * 4 + 2) * 64 + lb] = v.z;
            Xs[(lq * 4 + 3) * 64 + lb] = v.w;
        }
        __syncthreads();
#pragma unroll
        for (int kk = 0; kk < 16; kk++) {
            F4U wa, wb;
            wa.f = *(const float4*)&Ws[kk * 256 + j0a];
            wb.f = *(const float4*)&Ws[kk * 256 + j0b];
            float4 xa = *(const float4*)&Xs[kk * 64 + b0];
            float4 xb = *(const float4*)&Xs[kk * 64 + b0 + 4];
            unsigned long long xp[8] = {
                bcast2(xa.x), bcast2(xa.y), bcast2(xa.z), bcast2(xa.w),
                bcast2(xb.x), bcast2(xb.y), bcast2(xb.z), bcast2(xb.w)
            };
            unsigned long long wv[4] = { wa.u[0], wa.u[1], wb.u[0], wb.u[1] };
#pragma unroll
            for (int bi = 0; bi < 8; bi++)
#pragma unroll
                for (int p = 0; p < 4; p++)
                    acc[bi][p] = fma2(xp[bi], wv[p], acc[bi][p]);
        }
        __syncthreads();
    }

    float* zp = zpart + (size_t)ksplit * 64 * NJ;
#pragma unroll
    for (int bi = 0; bi < 8; bi++) {
        int b = b0 + bi;
        F4U oa, ob;
        oa.u[0] = acc[bi][0]; oa.u[1] = acc[bi][1];
        ob.u[0] = acc[bi][2]; ob.u[1] = acc[bi][3];
        *(float4*)&zp[b * NJ + jbase + j0a] = oa.f;
        *(float4*)&zp[b * NJ + jbase + j0b] = ob.f;
    }
}

// ---------------- LSTM gates (reduce 8 K-split partials, fixed order) ----------------
__device__ __forceinline__ void gates_phase(const float* __restrict__ zpart,
                                            const float* __restrict__ bias,
                                            float* __restrict__ h,
                                            float* __restrict__ c, int bid) {
#pragma unroll
    for (int r = 0; r < 2; r++) {
        int idx = bid * 256 + threadIdx.x + r * 32768;
        int b = idx >> 10;
        int u = idx & 1023;
        float zi = 0.f, zf = 0.f, zg = 0.f, zo = 0.f;
#pragma unroll
        for (int s = 0; s < 8; s++) {
            const float* base = zpart + ((size_t)s * 64 + b) * NJ4;
            zi += base[u];
            zf += base[1024 + u];
            zg += base[2048 + u];
            zo += base[3072 + u];
        }
        zi += bias[u];
        zf += bias[1024 + u];
        zg += bias[2048 + u];
        zo += bias[3072 + u];
        float cn = sigm(zf) * c[idx] + sigm(zi) * tanhf(zg);
        c[idx] = cn;
        h[idx] = sigm(zo) * tanhf(cn);
    }
}

// ---------------- log-softmax + argmax + out + nll (one block per batch row) ----------------
__device__ void softmax_phase(const float* __restrict__ zpart,
                              const float* __restrict__ linb,
                              const int* __restrict__ tag_ids, int tstep,
                              float* __restrict__ out, int b,
                              float* lg, float* rv, int* ri, float* rs) {
    int tid = threadIdx.x;

#pragma unroll
    for (int i = 0; i < 4; i++) {
        int u = tid + i * 256;
        float s = 0.f;
        for (int sp = 0; sp < 32; sp++)
            s += zpart[((size_t)sp * 64 + b) * 1024 + u];
        lg[u] = s + linb[u];
    }
    __syncthreads();

    float mv = lg[tid]; int mi = tid;
#pragma unroll
    for (int i = 1; i < 4; i++) {
        int u = tid + i * 256;
        float v = lg[u];
        if (v > mv) { mv = v; mi = u; }
    }
    rv[tid] = mv; ri[tid] = mi;
    __syncthreads();
    for (int off = 128; off > 0; off >>= 1) {
        if (tid < off) {
            float vo = rv[tid + off]; int io = ri[tid + off];
            if (vo > rv[tid] || (vo == rv[tid] && io < ri[tid])) {
                rv[tid] = vo; ri[tid] = io;
            }
        }
        __syncthreads();
    }
    float m = rv[0];

    float ps = 0.f;
#pragma unroll
    for (int i = 0; i < 4; i++) {
        int u = tid + i * 256;
        ps += expf(lg[u] - m);
    }
    rs[tid] = ps;
    __syncthreads();
    for (int off = 128; off > 0; off >>= 1) {
        if (tid < off) rs[tid] += rs[tid + off];
        __syncthreads();
    }
    float lse = m + logf(rs[0]);

#pragma unroll
    for (int i = 0; i < 4; i++) {
        int u = tid + i * 256;
        out[(size_t)tstep * (BSZ * HD) + b * HD + u] = lg[u] - lse;
    }

    if (tid == 0) {
        g_deint[b] = ri[0];
        int tg = tag_ids[b * TGTL + tstep];
        g_nll[tstep * BSZ + b] = (tg != 0) ? (lse - lg[tg]) : 0.0f;
    }
    __syncthreads();
}

// ---------------- the single persistent kernel ----------------
__global__ void __launch_bounds__(256, 1)
seq_main(const int* __restrict__ input_ids, const int* __restrict__ tag_ids,
         const float* __restrict__ enc_embed,
         const float* __restrict__ enc_Wih0, const float* __restrict__ enc_Whh0, const float* __restrict__ enc_b0,
         const float* __restrict__ enc_Wih1, const float* __restrict__ enc_Whh1, const float* __restrict__ enc_b1,
         const float* __restrict__ dec_embed,
         const float* __restrict__ dec_Wih0, const float* __restrict__ dec_Whh0, const float* __restrict__ dec_b0,
         const float* __restrict__ dec_Wih1, const float* __restrict__ dec_Whh1, const float* __restrict__ dec_b1,
         const float* __restrict__ dec_linW, const float* __restrict__ dec_linb,
         float* __restrict__ out, int out_size) {

    __shared__ float Xs[16 * 64];
    __shared__ float Ws[16 * 256];   // also reused as transpose tile (needs 1056 floats)
    __shared__ float lg[1024];
    __shared__ float rv[256];
    __shared__ int   ri[256];
    __shared__ float rs[256];
    __shared__ float stepv[TGTL];

    int bid = blockIdx.x;
    int t = threadIdx.x;

    // -------- phase 0: weight transposes + state init --------
    transp(g_Wenc0,                      NJ4, enc_Wih0, NJ4, ED, Ws, bid);
    transp(g_Wenc0 + (size_t)ED * NJ4,   NJ4, enc_Whh0, NJ4, HD, Ws, bid);
    transp(g_Wenc1,                      NJ4, enc_Wih1, NJ4, HD, Ws, bid);
    transp(g_Wenc1 + (size_t)HD * NJ4,   NJ4, enc_Whh1, NJ4, HD, Ws, bid);
    transp(g_Wdec0,                      NJ4, dec_Wih0, NJ4, ED, Ws, bid);
    transp(g_Wdec0 + (size_t)ED * NJ4,   NJ4, dec_Whh0, NJ4, HD, Ws, bid);
    transp(g_Wdec1,                      NJ4, dec_Wih1, NJ4, HD, Ws, bid);
    transp(g_Wdec1 + (size_t)HD * NJ4,   NJ4, dec_Whh1, NJ4, HD, Ws, bid);
    transp(g_linWT,                      HD,  dec_linW, HD,  HD, Ws, bid);

    for (int i = bid * 256 + t; i < BSZ * HD; i += NBLK * 256) {
        g_h0[i] = 0.f; g_c0[i] = 0.f; g_h1[i] = 0.f; g_c1[i] = 0.f;
    }
    if (bid == 0 && t < BSZ) g_deint[t] = 0;
    gsync();

    const int jt  = bid >> 3, ks  = bid & 7;    // cell GEMM: 16 j-tiles x 8 k-splits
    const int jtL = bid >> 5, ksL = bid & 31;   // logits  :  4 j-tiles x 32 k-splits

    // -------- encoder --------
    for (int ts = 0; ts < SRCL; ts++) {
        gemm_phase(g_Wenc0, enc_embed, input_ids, SRCL, ts, ED, g_h0, 192, NJ4, g_zpart, jt, ks, Xs, Ws);
        gsync();
        gates_phase(g_zpart, enc_b0, g_h0, g_c0, bid);
        gsync();
        gemm_phase(g_Wenc1, g_h0, (const int*)0, 0, 0, HD, g_h1, 256, NJ4, g_zpart, jt, ks, Xs, Ws);
        gsync();
        gates_phase(g_zpart, enc_b1, g_h1, g_c1, bid);
        gsync();
    }

    // -------- decoder --------
    for (int ts = 0; ts < TGTL; ts++) {
        gemm_phase(g_Wdec0, dec_embed, g_deint, 1, 0, ED, g_h0, 192, NJ4, g_zpart, jt, ks, Xs, Ws);
        gsync();
        gates_phase(g_zpart, dec_b0, g_h0, g_c0, bid);
        gsync();
        gemm_phase(g_Wdec1, g_h0, (const int*)0, 0, 0, HD, g_h1, 256, NJ4, g_zpart, jt, ks, Xs, Ws);
        gsync();
        gates_phase(g_zpart, dec_b1, g_h1, g_c1, bid);
        gsync();
        gemm_phase(g_linWT, g_h1, (const int*)0, 0, 0, HD, g_h1, 32, HD, g_zpart, jtL, ksL, Xs, Ws);
        gsync();
        if (bid < BSZ)
            softmax_phase(g_zpart, dec_linb, tag_ids, ts, out, bid, lg, rv, ri, rs);
        gsync();
    }

    // -------- loss (block 0) --------
    if (bid == 0) {
        if (t < TGTL) {
            int cnt = 0;
            float s = 0.f;
            for (int b = 0; b < BSZ; b++) {
                if (tag_ids[b * TGTL + t] != 0) cnt++;
                s += g_nll[t * BSZ + b];
            }
            int denom = cnt > 0 ? cnt : 1;
            stepv[t] = s / (float)denom;
        }
        __syncthreads();
        if (t == 0) {
            float total = 0.f;
            for (int i = 0; i < TGTL; i++) total += stepv[i];
            if (out_size > OUT_MAIN) out[OUT_MAIN] = total;
        }
    }
}

// ---------------- host launch: exactly ONE graph node ----------------
extern "C" void kernel_launch(void* const* d_in, const int* in_sizes, int n_in,
                              void* d_out, int out_size) {
    const int*   input_ids = (const int*)  d_in[0];
    const int*   tag_ids   = (const int*)  d_in[1];
    const float* enc_embed = (const float*)d_in[2];
    const float* enc_Wih0  = (const float*)d_in[3];
    const float* enc_Whh0  = (const float*)d_in[4];
    const float* enc_b0    = (const float*)d_in[5];
    const float* enc_Wih1  = (const float*)d_in[6];
    const float* enc_Whh1  = (const float*)d_in[7];
    const float* enc_b1    = (const float*)d_in[8];
    const float* dec_embed = (const float*)d_in[9];
    const float* dec_Wih0  = (const float*)d_in[10];
    const float* dec_Whh0  = (const float*)d_in[11];
    const float* dec_b0    = (const float*)d_in[12];
    const float* dec_Wih1  = (const float*)d_in[13];
    const float* dec_Whh1  = (const float*)d_in[14];
    const float* dec_b1    = (const float*)d_in[15];
    const float* dec_linW  = (const float*)d_in[16];
    const float* dec_linb  = (const float*)d_in[17];
    float* out = (float*)d_out;

    seq_main<<<NBLK, 256>>>(input_ids, tag_ids, enc_embed,
                            enc_Wih0, enc_Whh0, enc_b0,
                            enc_Wih1, enc_Whh1, enc_b1,
                            dec_embed,
                            dec_Wih0, dec_Whh0, dec_b0,
                            dec_Wih1, dec_Whh1, dec_b1,
                            dec_linW, dec_linb, out, out_size);
}

// round 5
// speedup vs baseline: 1.9640x; 1.9640x over previous
#include <cuda_runtime.h>
#include <cuda_fp16.h>
#include <math.h>
#include <stdint.h>

// ---------------- problem constants ----------------
#define BSZ   64
#define HD    1024
#define ED    512
#define SRCL  128
#define TGTL  128
#define NJ4   4096
#define NBLK  128
#define NTHR  256
#define OUT_MAIN (TGTL*BSZ*HD)

// ---------------- SMEM layout ----------------
// A plane: 128 rows x 64 halves (128B rows, SW128) = 16KB ; B plane: 64 x 64 = 8KB
#define ABUF(buf,pl) ((buf)*49152 + (pl)*16384)
#define BBUF(buf,pl) ((buf)*49152 + 32768 + (pl)*8192)
#define OFF_LG     98304
#define OFF_RV     (OFF_LG + 4096)
#define OFF_RI     (OFF_RV + 1024)
#define OFF_RS     (OFF_RI + 1024)
#define OFF_STEPV  (OFF_RS + 1024)
#define SMEM_TOTAL (OFF_STEPV + 512 + 128)

#define SW(o) ((o) ^ (((o) >> 3) & 0x70))

// ---------------- device scratch (static, no allocs) ----------------
__device__ __half g_e0w1[4096*1536], g_e0w2[4096*1536];
__device__ __half g_e1w1[4096*2048], g_e1w2[4096*2048];
__device__ __half g_d0w1[4096*1536], g_d0w2[4096*1536];
__device__ __half g_d1w1[4096*2048], g_d1w2[4096*2048];
__device__ __half g_lnw1[1024*1024], g_lnw2[1024*1024];
__device__ __half g_xe1[SRCL*BSZ*ED], g_xe2[SRCL*BSZ*ED];
__device__ __half g_xd1[BSZ*ED], g_xd2[BSZ*ED];
__device__ __half g_h0p1[BSZ*HD], g_h0p2[BSZ*HD];
__device__ __half g_h1p1[BSZ*HD], g_h1p2[BSZ*HD];
__device__ float  g_c0f[BSZ*HD], g_c1f[BSZ*HD];
__device__ float  g_zpart[1048576];
__device__ float  g_nll[TGTL*BSZ];
__device__ unsigned g_cnt;
__device__ volatile unsigned g_gen;

// ---------------- helpers ----------------
__device__ __forceinline__ float sigm(float x) { return 1.0f / (1.0f + expf(-x)); }

__device__ __forceinline__ uint32_t smem_u32(const void* p) {
    uint32_t a;
    asm("{ .reg .u64 t; cvta.to.shared.u64 t, %1; cvt.u32.u64 %0, t; }" : "=r"(a) : "l"(p));
    return a;
}
__device__ __forceinline__ void cp_async16(uint32_t dst, const void* src) {
    asm volatile("cp.async.cg.shared.global [%0], [%1], 16;" :: "r"(dst), "l"(src) : "memory");
}
__device__ __forceinline__ void ldsm4(uint32_t* r, uint32_t addr) {
    asm volatile("ldmatrix.sync.aligned.m8n8.x4.shared.b16 {%0,%1,%2,%3}, [%4];"
                 : "=r"(r[0]), "=r"(r[1]), "=r"(r[2]), "=r"(r[3]) : "r"(addr));
}
__device__ __forceinline__ void mma16816(float* d, const uint32_t* a, const uint32_t* b) {
    asm volatile(
        "mma.sync.aligned.m16n8k16.row.col.f32.f16.f16.f32 "
        "{%0,%1,%2,%3}, {%4,%5,%6,%7}, {%8,%9}, {%0,%1,%2,%3};"
        : "+f"(d[0]), "+f"(d[1]), "+f"(d[2]), "+f"(d[3])
        : "r"(a[0]), "r"(a[1]), "r"(a[2]), "r"(a[3]), "r"(b[0]), "r"(b[1]));
}
__device__ __forceinline__ void hsplit(float v, __half* a, __half* b) {
    __half x = __float2half_rn(v);
    *a = x;
    *b = __float2half_rn(v - __half2float(x));
}

// ---------------- grid barrier ----------------
__device__ __forceinline__ void gsync() {
    __syncthreads();
    if (threadIdx.x == 0) {
        __threadfence();
        unsigned gen = g_gen;
        if (atomicAdd(&g_cnt, 1u) == NBLK - 1u) {
            g_cnt = 0u;
            __threadfence();
            g_gen = gen + 1u;
        } else {
            while (g_gen == gen) { __nanosleep(64); }
        }
        __threadfence();
    }
    __syncthreads();
}

// ---------------- chunk loader (64 k, both planes of A and B) ----------------
__device__ __forceinline__ void load_chunk(
    const __half* __restrict__ W1, const __half* __restrict__ W2, int K,
    const __half* __restrict__ xp1, const __half* __restrict__ xp2, int K1,
    const __half* __restrict__ hp1, const __half* __restrict__ hp2,
    int jbase, int kb, uint32_t su, int buf) {
    int t = threadIdx.x;
#pragma unroll
    for (int pl = 0; pl < 2; pl++) {
        const __half* Wp = pl ? W2 : W1;
#pragma unroll
        for (int i = 0; i < 4; i++) {
            int idx = t + i * 256;
            int row = idx >> 3, seg = idx & 7;
            const __half* src = Wp + (size_t)(jbase + row) * K + kb + seg * 8;
            cp_async16(su + ABUF(buf, pl) + SW(row * 128 + seg * 16), src);
        }
    }
#pragma unroll
    for (int pl = 0; pl < 2; pl++) {
        const __half* xp = pl ? xp2 : xp1;
        const __half* hp = pl ? hp2 : hp1;
#pragma unroll
        for (int i = 0; i < 2; i++) {
            int idx = t + i * 256;
            int row = idx >> 3, seg = idx & 7;
            int k = kb + seg * 8;
            const __half* src = (k < K1) ? xp + (size_t)row * K1 + k
                                         : hp + (size_t)row * HD + (k - K1);
            cp_async16(su + BBUF(buf, pl) + SW(row * 128 + seg * 16), src);
        }
    }
    asm volatile("cp.async.commit_group;" ::: "memory");
}

// ---------------- tensor-core GEMM: z[64b x NJ] tile 128j x 64b, fp16 split-2 ----------------
__device__ void tc_gemm(const __half* __restrict__ W1, const __half* __restrict__ W2, int K,
                        const __half* __restrict__ xp1, const __half* __restrict__ xp2, int K1,
                        const __half* __restrict__ hp1, const __half* __restrict__ hp2,
                        int jbase, int kbase, int nchunk, int NJ,
                        float* __restrict__ zout, uint32_t su) {
    int t = threadIdx.x, lane = t & 31, w = t >> 5;
    int wm = w & 3, wn = w >> 2;
    int m0 = wm * 32, n0 = wn * 32;

    float acc[2][4][4];
#pragma unroll
    for (int a = 0; a < 2; a++)
#pragma unroll
        for (int b = 0; b < 4; b++)
#pragma unroll
            for (int cc = 0; cc < 4; cc++) acc[a][b][cc] = 0.f;

    load_chunk(W1, W2, K, xp1, xp2, K1, hp1, hp2, jbase, kbase, su, 0);

    for (int c = 0; c < nchunk; c++) {
        int buf = c & 1;
        if (c + 1 < nchunk) {
            load_chunk(W1, W2, K, xp1, xp2, K1, hp1, hp2, jbase, kbase + (c + 1) * 64, su, buf ^ 1);
            asm volatile("cp.async.wait_group 1;" ::: "memory");
        } else {
            asm volatile("cp.async.wait_group 0;" ::: "memory");
        }
        __syncthreads();

        uint32_t a1b = su + ABUF(buf, 0), a2b = su + ABUF(buf, 1);
        uint32_t b1b = su + BBUF(buf, 0), b2b = su + BBUF(buf, 1);
#pragma unroll
        for (int ks = 0; ks < 4; ks++) {
            uint32_t a1[2][4], a2[2][4];
            int arow = m0 + (lane & 15);
            int aseg = ks * 2 + (lane >> 4);
#pragma unroll
            for (int mi = 0; mi < 2; mi++) {
                uint32_t off = SW((arow + mi * 16) * 128 + aseg * 16);
                ldsm4(a1[mi], a1b + off);
                ldsm4(a2[mi], a2b + off);
            }
#pragma unroll
            for (int nb = 0; nb < 2; nb++) {
                int nrow = n0 + nb * 16 + ((lane >> 4) << 3) + (lane & 7);
                int bseg = ks * 2 + ((lane >> 3) & 1);
                uint32_t off = SW(nrow * 128 + bseg * 16);
                uint32_t b1[4], b2[4];
                ldsm4(b1, b1b + off);
                ldsm4(b2, b2b + off);
#pragma unroll
                for (int mi = 0; mi < 2; mi++) {
                    mma16816(acc[mi][nb * 2],     a1[mi], b1);
                    mma16816(acc[mi][nb * 2],     a1[mi], b2);
                    mma16816(acc[mi][nb * 2],     a2[mi], b1);
                    mma16816(acc[mi][nb * 2 + 1], a1[mi], b1 + 2);
                    mma16816(acc[mi][nb * 2 + 1], a1[mi], b2 + 2);
                    mma16816(acc[mi][nb * 2 + 1], a2[mi], b1 + 2);
                }
            }
        }
        __syncthreads();
    }

    // epilogue: z[b][j]
    int g = lane >> 2, q = lane & 3;
#pragma unroll
    for (int mi = 0; mi < 2; mi++)
#pragma unroll
        for (int nf = 0; nf < 4; nf++) {
            int j = jbase + m0 + mi * 16 + g;
            int b = n0 + nf * 8 + q * 2;
            zout[(size_t)b * NJ + j]           = acc[mi][nf][0];
            zout[(size_t)(b + 1) * NJ + j]     = acc[mi][nf][1];
            zout[(size_t)b * NJ + j + 8]       = acc[mi][nf][2];
            zout[(size_t)(b + 1) * NJ + j + 8] = acc[mi][nf][3];
        }
}

// ---------------- LSTM gates: reduce 4 k-splits, emit h plane pair ----------------
__device__ void gates_phase(const float* __restrict__ zpart, const float* __restrict__ bias,
                            float* __restrict__ c, __half* __restrict__ hp1,
                            __half* __restrict__ hp2, int bid) {
#pragma unroll
    for (int r = 0; r < 2; r++) {
        int idx = bid * 256 + threadIdx.x + r * 32768;
        int b = idx >> 10, u = idx & 1023;
        float zi = 0.f, zf = 0.f, zg = 0.f, zo = 0.f;
#pragma unroll
        for (int s = 0; s < 4; s++) {
            const float* base = zpart + ((size_t)s * 64 + b) * NJ4;
            zi += base[u]; zf += base[1024 + u];
            zg += base[2048 + u]; zo += base[3072 + u];
        }
        zi += bias[u]; zf += bias[1024 + u]; zg += bias[2048 + u]; zo += bias[3072 + u];
        float cn = sigm(zf) * c[idx] + sigm(zi) * tanhf(zg);
        c[idx] = cn;
        float hn = sigm(zo) * tanhf(cn);
        hsplit(hn, &hp1[idx], &hp2[idx]);
    }
}

// ---------------- the single persistent kernel ----------------
__global__ void __launch_bounds__(NTHR, 1)
seq_main(const int* __restrict__ input_ids, const int* __restrict__ tag_ids,
         const float* __restrict__ enc_embed,
         const float* __restrict__ enc_Wih0, const float* __restrict__ enc_Whh0, const float* __restrict__ enc_b0,
         const float* __restrict__ enc_Wih1, const float* __restrict__ enc_Whh1, const float* __restrict__ enc_b1,
         const float* __restrict__ dec_embed,
         const float* __restrict__ dec_Wih0, const float* __restrict__ dec_Whh0, const float* __restrict__ dec_b0,
         const float* __restrict__ dec_Wih1, const float* __restrict__ dec_Whh1, const float* __restrict__ dec_b1,
         const float* __restrict__ dec_linW, const float* __restrict__ dec_linb,
         float* __restrict__ out, int out_size) {
    extern __shared__ char smem[];
    uint32_t su = smem_u32(smem);
    int bid = blockIdx.x;
    int t = threadIdx.x;
    int gid = bid * NTHR + t;

    // ---- phase 0: weight plane splits (concat along K), embed prep, state init ----
    for (int i = gid; i < 4096 * 512; i += NBLK * NTHR) {
        int r = i >> 9, k = i & 511;
        hsplit(enc_Wih0[i], &g_e0w1[(size_t)r * 1536 + k], &g_e0w2[(size_t)r * 1536 + k]);
        hsplit(dec_Wih0[i], &g_d0w1[(size_t)r * 1536 + k], &g_d0w2[(size_t)r * 1536 + k]);
    }
    for (int i = gid; i < 4096 * 1024; i += NBLK * NTHR) {
        int r = i >> 10, k = i & 1023;
        size_t o0 = (size_t)r * 1536 + 512 + k;
        hsplit(enc_Whh0[i], &g_e0w1[o0], &g_e0w2[o0]);
        hsplit(dec_Whh0[i], &g_d0w1[o0], &g_d0w2[o0]);
        size_t o1 = (size_t)r * 2048 + k;
        hsplit(enc_Wih1[i], &g_e1w1[o1], &g_e1w2[o1]);
        hsplit(dec_Wih1[i], &g_d1w1[o1], &g_d1w2[o1]);
        size_t o2 = o1 + 1024;
        hsplit(enc_Whh1[i], &g_e1w1[o2], &g_e1w2[o2]);
        hsplit(dec_Whh1[i], &g_d1w1[o2], &g_d1w2[o2]);
    }
    for (int i = gid; i < 1024 * 1024; i += NBLK * NTHR)
        hsplit(dec_linW[i], &g_lnw1[i], &g_lnw2[i]);

    for (int i = gid; i < SRCL * BSZ * ED; i += NBLK * NTHR) {
        int step = i / (BSZ * ED);
        int r = i % (BSZ * ED);
        int b = r / ED, k = r % ED;
        int id = input_ids[b * SRCL + step];
        hsplit(enc_embed[(size_t)id * ED + k], &g_xe1[i], &g_xe2[i]);
    }
    if (bid == 0) {
        for (int i = t; i < BSZ * ED; i += NTHR) {
            int k = i % ED;
            hsplit(dec_embed[k], &g_xd1[i], &g_xd2[i]);
        }
    }
    for (int i = gid; i < BSZ * HD; i += NBLK * NTHR) {
        g_c0f[i] = 0.f; g_c1f[i] = 0.f;
        g_h0p1[i] = __half(0.f); g_h0p2[i] = __half(0.f);
        g_h1p1[i] = __half(0.f); g_h1p2[i] = __half(0.f);
    }
    gsync();

    const int jt = bid >> 2, ks = bid & 3;      // cells: 32 j-tiles x 4 k-splits
    const int jtL = bid >> 4, ksL = bid & 15;   // logits: 8 j-tiles x 16 k-splits

    // -------- encoder --------
    for (int ts = 0; ts < SRCL; ts++) {
        tc_gemm(g_e0w1, g_e0w2, 1536,
                g_xe1 + (size_t)ts * BSZ * ED, g_xe2 + (size_t)ts * BSZ * ED, ED,
                g_h0p1, g_h0p2, jt * 128, ks * 384, 6, NJ4,
                g_zpart + (size_t)ks * 64 * NJ4, su);
        gsync();
        gates_phase(g_zpart, enc_b0, g_c0f, g_h0p1, g_h0p2, bid);
        gsync();
        tc_gemm(g_e1w1, g_e1w2, 2048, g_h0p1, g_h0p2, HD, g_h1p1, g_h1p2,
                jt * 128, ks * 512, 8, NJ4, g_zpart + (size_t)ks * 64 * NJ4, su);
        gsync();
        gates_phase(g_zpart, enc_b1, g_c1f, g_h1p1, g_h1p2, bid);
        gsync();
    }

    // -------- decoder --------
    float* lg = (float*)(smem + OFF_LG);
    float* rv = (float*)(smem + OFF_RV);
    int*   ri = (int*)(smem + OFF_RI);
    float* rs = (float*)(smem + OFF_RS);

    for (int ts = 0; ts < TGTL; ts++) {
        tc_gemm(g_d0w1, g_d0w2, 1536, g_xd1, g_xd2, ED, g_h0p1, g_h0p2,
                jt * 128, ks * 384, 6, NJ4, g_zpart + (size_t)ks * 64 * NJ4, su);
        gsync();
        gates_phase(g_zpart, dec_b0, g_c0f, g_h0p1, g_h0p2, bid);
        gsync();
        tc_gemm(g_d1w1, g_d1w2, 2048, g_h0p1, g_h0p2, HD, g_h1p1, g_h1p2,
                jt * 128, ks * 512, 8, NJ4, g_zpart + (size_t)ks * 64 * NJ4, su);
        gsync();
        gates_phase(g_zpart, dec_b1, g_c1f, g_h1p1, g_h1p2, bid);
        gsync();
        tc_gemm(g_lnw1, g_lnw2, 1024, g_h1p1, g_h1p2, HD, g_h1p1, g_h1p2,
                jtL * 128, ksL * 64, 1, HD, g_zpart + (size_t)ksL * 64 * HD, su);
        gsync();

        if (bid < BSZ) {
            int b = bid;
#pragma unroll
            for (int i = 0; i < 4; i++) {
                int u = t + i * 256;
                float s = 0.f;
                for (int sp = 0; sp < 16; sp++)
                    s += g_zpart[((size_t)sp * 64 + b) * HD + u];
                lg[u] = s + dec_linb[u];
            }
            __syncthreads();
            float mv = lg[t]; int mi = t;
#pragma unroll
            for (int i = 1; i < 4; i++) {
                int u = t + i * 256;
                float v = lg[u];
                if (v > mv) { mv = v; mi = u; }
            }
            rv[t] = mv; ri[t] = mi;
            __syncthreads();
            for (int off = 128; off > 0; off >>= 1) {
                if (t < off) {
                    float vo = rv[t + off]; int io = ri[t + off];
                    if (vo > rv[t] || (vo == rv[t] && io < ri[t])) { rv[t] = vo; ri[t] = io; }
                }
                __syncthreads();
            }
            float m = rv[0];
            float ps = 0.f;
#pragma unroll
            for (int i = 0; i < 4; i++) ps += expf(lg[t + i * 256] - m);
            rs[t] = ps;
            __syncthreads();
            for (int off = 128; off > 0; off >>= 1) {
                if (t < off) rs[t] += rs[t + off];
                __syncthreads();
            }
            float lse = m + logf(rs[0]);
#pragma unroll
            for (int i = 0; i < 4; i++) {
                int u = t + i * 256;
                out[(size_t)ts * (BSZ * HD) + b * HD + u] = lg[u] - lse;
            }
            int mi0 = ri[0];
            for (int k = t; k < ED; k += NTHR)
                hsplit(dec_embed[(size_t)mi0 * ED + k], &g_xd1[b * ED + k], &g_xd2[b * ED + k]);
            if (t == 0) {
                int tg = tag_ids[b * TGTL + ts];
                g_nll[ts * BSZ + b] = (tg != 0) ? (lse - lg[tg]) : 0.0f;
            }
            __syncthreads();
        }
        gsync();
    }

    // -------- loss (block 0) --------
    if (bid == 0) {
        float* stepv = (float*)(smem + OFF_STEPV);
        if (t < TGTL) {
            int cnt = 0;
            float s = 0.f;
            for (int b = 0; b < BSZ; b++) {
                if (tag_ids[b * TGTL + t] != 0) cnt++;
                s += g_nll[t * BSZ + b];
            }
            stepv[t] = s / (float)(cnt > 0 ? cnt : 1);
        }
        __syncthreads();
        if (t == 0) {
            float total = 0.f;
            for (int i = 0; i < TGTL; i++) total += stepv[i];
            if (out_size > OUT_MAIN) out[OUT_MAIN] = total;
        }
    }
}

// ---------------- host launch: ONE graph node ----------------
extern "C" void kernel_launch(void* const* d_in, const int* in_sizes, int n_in,
                              void* d_out, int out_size) {
    cudaFuncSetAttribute(seq_main, cudaFuncAttributeMaxDynamicSharedMemorySize, SMEM_TOTAL);
    seq_main<<<NBLK, NTHR, SMEM_TOTAL>>>(
        (const int*)d_in[0], (const int*)d_in[1], (const float*)d_in[2],
        (const float*)d_in[3], (const float*)d_in[4], (const float*)d_in[5],
        (const float*)d_in[6], (const float*)d_in[7], (const float*)d_in[8],
        (const float*)d_in[9],
        (const float*)d_in[10], (const float*)d_in[11], (const float*)d_in[12],
        (const float*)d_in[13], (const float*)d_in[14], (const float*)d_in[15],
        (const float*)d_in[16], (const float*)d_in[17],
        (float*)d_out, out_size);
}